// round 2
// baseline (speedup 1.0000x reference)
#include <cuda_runtime.h>

// BKT_RNN: T=1024 timesteps, B=4096 independent chains, H=4 hidden.
// One thread per chain. 128 blocks x 32 threads = 4096 threads (1 warp/SM).
//
// Round 2: software-pipelined step (BKT of step t-1 overlaps MUFU pacing of
// step t), f32x2-packed matvec, fused deterministic loss reduction.
//
// Math (exact up to fp rounding):
//  1) BKT m_t == latent identically, so latent' = latent*(r1+r0-1) + (1-r0),
//     correct = latent*(r3+r2-1) + (1-r2).
//  2) r-form tanh: h = 1-2r, r = 1/(exp(2z)+1); params p_j = 1-r_j.

#define Tn 1024
#define Bn 4096
#define NBLK 128
#define NTHR 32

typedef unsigned long long u64;

__device__ float    g_part[NBLK];
__device__ unsigned g_ctr = 0;

__device__ __forceinline__ float ex2_f(float a){ float r; asm("ex2.approx.f32 %0, %1;" : "=f"(r) : "f"(a)); return r; }
__device__ __forceinline__ float rcp_f(float a){ float r; asm("rcp.approx.f32 %0, %1;" : "=f"(r) : "f"(a)); return r; }
__device__ __forceinline__ float lg2_f(float a){ float r; asm("lg2.approx.f32 %0, %1;" : "=f"(r) : "f"(a)); return r; }

__device__ __forceinline__ u64 pk(float lo, float hi){ u64 d; asm("mov.b64 %0,{%1,%2};" : "=l"(d) : "f"(lo),"f"(hi)); return d; }
__device__ __forceinline__ void upk(u64 d, float& lo, float& hi){ asm("mov.b64 {%0,%1},%2;" : "=f"(lo),"=f"(hi) : "l"(d)); }
__device__ __forceinline__ u64 ffma2(u64 a, u64 b, u64 c){ u64 d; asm("fma.rn.f32x2 %0,%1,%2,%3;" : "=l"(d) : "l"(a),"l"(b),"l"(c)); return d; }

__global__ __launch_bounds__(NTHR, 1) void bkt_main(
    const float* __restrict__ x, const float* __restrict__ y,
    const float* __restrict__ prior,
    const float* __restrict__ W_ih, const float* __restrict__ W_hh,
    const float* __restrict__ b_ih, const float* __restrict__ b_hh,
    float* __restrict__ out)
{
    const int b = blockIdx.x * NTHR + threadIdx.x;
    const float L2E2 = 2.8853900817779268f;   // 2*log2(e)

    // Pre-scaled weights, packed for f32x2: pair 01 = units (0,1), pair 23 = (2,3)
    float C0s[4], Cxs[4], Wp[4][4];
    #pragma unroll
    for (int j = 0; j < 4; j++) {
        float S = 0.f;
        #pragma unroll
        for (int k = 0; k < 4; k++) {
            float w = W_hh[j * 4 + k];
            Wp[j][k] = -2.f * L2E2 * w;      // -4*log2e*W  (matvec over r)
            S += w;
        }
        C0s[j] = L2E2 * (b_ih[j] + b_hh[j] + S);
        Cxs[j] = L2E2 * W_ih[j];
    }
    u64 C001 = pk(C0s[0], C0s[1]), C023 = pk(C0s[2], C0s[3]);
    u64 Cx01 = pk(Cxs[0], Cxs[1]), Cx23 = pk(Cxs[2], Cxs[3]);
    u64 W01[4], W23[4];
    #pragma unroll
    for (int k = 0; k < 4; k++) {
        W01[k] = pk(Wp[0][k], Wp[1][k]);
        W23[k] = pk(Wp[2][k], Wp[3][k]);
    }

    // latent0 = sigmoid(prior)
    float pz = prior[0];
    float latent = 1.f / (1.f + ex2_f(-pz * 1.4426950408889634f));

    const float* xp = x + b;
    const float* yp = y + b;
    float* __restrict__ oc = out + b;                    // corrects [0, T*B)
    float* __restrict__ ol = out + (size_t)Tn * Bn + b;  // latents  [T*B, 2*T*B)

    float r0 = 0.5f, r1 = 0.5f, r2 = 0.5f, r3 = 0.5f;   // h=0 -> r=0.5
    float lacc = 0.f;
    float u0v, u1v, u2v, u3v;

    float xA[8], yA[8], xB[8], yB[8];
    #pragma unroll
    for (int u = 0; u < 8; u++) { xA[u] = xp[u * Bn]; yA[u] = yp[u * Bn]; }

    // Prologue: u for t=0 (r = 0.5)
    {
        u64 xx = pk(xA[0], xA[0]);
        u64 a01 = ffma2(xx, Cx01, C001);
        u64 a23 = ffma2(xx, Cx23, C023);
        u64 hh = pk(0.5f, 0.5f);
        #pragma unroll
        for (int k = 0; k < 4; k++) { a01 = ffma2(hh, W01[k], a01); a23 = ffma2(hh, W23[k], a23); }
        upk(a01, u0v, u1v); upk(a23, u2v, u3v);
    }

    float yPrev = 0.f;

    // Iteration t: ex2(u_t) -> [BKT for t-1, fills MUFU pacing] -> rcp -> r_t
    //              -> matvec with x_{t+1} -> u_{t+1}
    auto body = [&](int t, float xn, float ypv, bool doBKT, bool doMat) {
        float E0 = ex2_f(u0v), E1 = ex2_f(u1v), E2 = ex2_f(u2v), E3 = ex2_f(u3v);
        if (doBKT) {
            // r0..r3 still hold step t-1 values here
            float Ac = (r3 + r2) - 1.f;
            float g  = 1.f - r2;
            float correct = fmaf(latent, Ac, g);
            float omc     = fmaf(-latent, Ac, r2);
            float Al = (r1 + r0) - 1.f;
            float l  = 1.f - r0;
            float latn = fmaf(latent, Al, l);
            float pe = fmaf(ypv, correct - omc, omc);
            float ll = fmaxf(lg2_f(pe) * 0.69314718055994531f, -100.f);
            lacc += ll;
            oc[(size_t)(t - 1) * Bn] = correct;
            ol[(size_t)(t - 1) * Bn] = latn;
            latent = latn;
        }
        r0 = rcp_f(E0 + 1.f);
        r1 = rcp_f(E1 + 1.f);
        r2 = rcp_f(E2 + 1.f);
        r3 = rcp_f(E3 + 1.f);
        if (doMat) {
            u64 xx  = pk(xn, xn);
            u64 a01 = ffma2(xx, Cx01, C001);
            u64 a23 = ffma2(xx, Cx23, C023);
            u64 rr0 = pk(r0, r0); a01 = ffma2(rr0, W01[0], a01); a23 = ffma2(rr0, W23[0], a23);
            u64 rr1 = pk(r1, r1); a01 = ffma2(rr1, W01[1], a01); a23 = ffma2(rr1, W23[1], a23);
            u64 rr2 = pk(r2, r2); a01 = ffma2(rr2, W01[2], a01); a23 = ffma2(rr2, W23[2], a23);
            u64 rr3 = pk(r3, r3); a01 = ffma2(rr3, W01[3], a01); a23 = ffma2(rr3, W23[3], a23);
            upk(a01, u0v, u1v); upk(a23, u2v, u3v);
        }
    };

    for (int t0 = 0; t0 < Tn; t0 += 16) {
        // prefetch steps t0+8 .. t0+15 (always in range: t0 <= 1008)
        {
            const float* xq = xp + (size_t)(t0 + 8) * Bn;
            const float* yq = yp + (size_t)(t0 + 8) * Bn;
            #pragma unroll
            for (int u = 0; u < 8; u++) { xB[u] = xq[u * Bn]; yB[u] = yq[u * Bn]; }
        }
        #pragma unroll
        for (int u = 0; u < 8; u++) {
            int   t   = t0 + u;
            float xn  = (u < 7) ? xA[u + 1] : xB[0];
            float ypv = (u > 0) ? yA[u - 1] : yPrev;
            body(t, xn, ypv, (u > 0) || (t0 > 0), true);
        }
        yPrev = yA[7];

        if (t0 + 16 < Tn) {
            const float* xq = xp + (size_t)(t0 + 16) * Bn;
            const float* yq = yp + (size_t)(t0 + 16) * Bn;
            #pragma unroll
            for (int u = 0; u < 8; u++) { xA[u] = xq[u * Bn]; yA[u] = yq[u * Bn]; }
        }
        #pragma unroll
        for (int u = 0; u < 8; u++) {
            int   t   = t0 + 8 + u;
            float xn  = (u < 7) ? xB[u + 1] : xA[0];   // xA holds next group (stale+unused on last step)
            float ypv = (u > 0) ? yB[u - 1] : yA[7];
            body(t, xn, ypv, true, t < Tn - 1);
        }
        yPrev = yB[7];
    }

    // Epilogue: BKT for t=1023 (r0..r3 hold step-1023 values)
    {
        float Ac = (r3 + r2) - 1.f;
        float g  = 1.f - r2;
        float correct = fmaf(latent, Ac, g);
        float omc     = fmaf(-latent, Ac, r2);
        float Al = (r1 + r0) - 1.f;
        float l  = 1.f - r0;
        float latn = fmaf(latent, Al, l);
        float pe = fmaf(yPrev, correct - omc, omc);
        float ll = fmaxf(lg2_f(pe) * 0.69314718055994531f, -100.f);
        lacc += ll;
        oc[(size_t)(Tn - 1) * Bn] = correct;
        ol[(size_t)(Tn - 1) * Bn] = latn;
    }

    // Deterministic loss: warp reduce -> per-block partial -> last block sums
    #pragma unroll
    for (int o = 16; o; o >>= 1) lacc += __shfl_xor_sync(0xffffffffu, lacc, o);

    __shared__ unsigned sLast;
    if (threadIdx.x == 0) {
        g_part[blockIdx.x] = lacc;
        __threadfence();
        unsigned ticket = atomicAdd(&g_ctr, 1u);
        sLast = (ticket == NBLK - 1) ? 1u : 0u;
    }
    __syncthreads();
    if (sLast) {
        __threadfence();  // acquire: make all g_part writes visible
        int tid = threadIdx.x;
        float v = g_part[tid] + g_part[tid + 32] + g_part[tid + 64] + g_part[tid + 96];
        #pragma unroll
        for (int o = 16; o; o >>= 1) v += __shfl_xor_sync(0xffffffffu, v, o);
        if (tid == 0) {
            out[(size_t)2 * Tn * Bn] = -v / (float)((size_t)Tn * Bn);
            __threadfence();
            g_ctr = 0;   // reset for next graph replay
        }
    }
}

extern "C" void kernel_launch(void* const* d_in, const int* in_sizes, int n_in,
                              void* d_out, int out_size)
{
    (void)in_sizes; (void)n_in; (void)out_size;
    const float* x     = (const float*)d_in[0];
    const float* y     = (const float*)d_in[1];
    const float* prior = (const float*)d_in[2];
    const float* W_ih  = (const float*)d_in[3];
    const float* W_hh  = (const float*)d_in[4];
    const float* b_ih  = (const float*)d_in[5];
    const float* b_hh  = (const float*)d_in[6];
    float* out = (float*)d_out;

    bkt_main<<<NBLK, NTHR>>>(x, y, prior, W_ih, W_hh, b_ih, b_hh, out);
}